// round 16
// baseline (speedup 1.0000x reference)
#include <cuda_runtime.h>
#include <cuda_fp16.h>

#define N_NODES 12288
#define DIM 64
#define N_EDGES 262144
#define EPS_F 0.01f

// Repacked storage: r rows compressed to fp16 (64 halfs = 128B = ONE cache
// line per row); per-NODE exp(-m) table (48KB, L1-resident in edge kernel).
__device__ __half g_rh[N_NODES * DIM];
__device__ float  g_xn[N_NODES];   // exp(-m[node])

// Pre-pass, 196608 threads: pure transpose (4 coalesced LDG + 1 STG.64 each)
// + per-node exp(-m) (12288 of them).
__global__ void __launch_bounds__(256) repack_kernel(const float* __restrict__ z) {
    int t = blockIdx.x * blockDim.x + threadIdx.x;
    const int quads = N_NODES * DIM / 4;   // 196608

    if (t < quads) {
        int row = t >> 4;          // 16 quads per 64-wide row
        int col = (t & 15) << 2;
        const float* src = z + row * 65 + col;
        float x0 = src[0];
        float x1 = src[1];
        float x2 = src[2];
        float x3 = src[3];
        __half2 h0 = __floats2half2_rn(x0, x1);
        __half2 h1 = __floats2half2_rn(x2, x3);
        uint2 w;
        w.x = *reinterpret_cast<unsigned*>(&h0);
        w.y = *reinterpret_cast<unsigned*>(&h1);
        *reinterpret_cast<uint2*>(g_rh + (size_t)t * 4) = w;
    }
    if (t < N_NODES) {
        g_xn[t] = __expf(-z[t * 65 + 64]);
    }
}

// Accumulate ||a-b||^2 contribution of one 16B chunk (8 halfs), fp32 math.
__device__ __forceinline__ float sq_chunk(const uint4& pa, const uint4& pb) {
    const __half2* ha = reinterpret_cast<const __half2*>(&pa);
    const __half2* hb = reinterpret_cast<const __half2*>(&pb);
    float acc = 0.0f;
    #pragma unroll
    for (int k = 0; k < 4; k++) {
        float2 fa = __half22float2(ha[k]);
        float2 fb = __half22float2(hb[k]);
        float dx = fa.x - fb.x;
        float dy = fa.y - fb.y;
        acc = fmaf(dx, dx, acc);
        acc = fmaf(dy, dy, acc);
    }
    return acc;
}

// Warp owns 16 consecutive edges as 2 rounds of 8 (8-lane groups, 2 edges
// per thread per round). 16-edge tiles -> 16384 warps -> ~1.7 waves on the
// chip: wave 2 backfills as early blocks drain, smoothing the single-wave
// drain tail seen at 32-edge tiles (achieved occ 54.6% vs ~86% resident).
// Tail: lanes 0..15 each own one edge (others idle through a short tail).
__global__ void __launch_bounds__(256) edge_kernel(
        const int* __restrict__ eidx,
        const float* __restrict__ lptr,
        float4* __restrict__ out) {
    unsigned tid  = blockIdx.x * blockDim.x + threadIdx.x;
    unsigned warp = tid >> 5;
    unsigned lane = tid & 31u;
    unsigned base = warp * 16u;        // first of this warp's 16 edges
    unsigned i    = lane & 7u;         // lane within 8-group
    unsigned grp  = lane >> 3;         // group 0..3

    const uint4* __restrict__ rb = reinterpret_cast<const uint4*>(g_rh);
    float l = __ldg(lptr);

    // Prologue: my tail edge's node indices + exp(-m) gathers (lanes 0..15
    // own edges; others load a duplicate, harmless). Consumed in the tail,
    // ~1000+ cycles later.
    unsigned e_mine = base + (lane & 15u);
    int u_mine = eidx[e_mine];
    int v_mine = eidx[N_EDGES + e_mine];
    float xu = g_xn[u_mine];
    float xv = g_xn[v_mine];

    float myacc = 0.0f;

    #pragma unroll
    for (unsigned r = 0; r < 2; r++) {
        unsigned e0 = base + r * 8u + grp * 2u;

        // Merged index loads (uniform within group).
        int2 uu = *reinterpret_cast<const int2*>(eidx + e0);
        int2 vv = *reinterpret_cast<const int2*>(eidx + N_EDGES + e0);

        // Payload: 4 independent LDG.128 (one full 128B row each).
        uint4 pa0 = rb[uu.x * 8 + i];
        uint4 pb0 = rb[vv.x * 8 + i];
        uint4 pa1 = rb[uu.y * 8 + i];
        uint4 pb1 = rb[vv.y * 8 + i];

        float acc0 = sq_chunk(pa0, pb0);
        float acc1 = sq_chunk(pa1, pb1);

        // Butterfly reduce: all 8 lanes of the group end with the full sum.
        acc0 += __shfl_xor_sync(0xffffffffu, acc0, 4);
        acc1 += __shfl_xor_sync(0xffffffffu, acc1, 4);
        acc0 += __shfl_xor_sync(0xffffffffu, acc0, 2);
        acc1 += __shfl_xor_sync(0xffffffffu, acc1, 2);
        acc0 += __shfl_xor_sync(0xffffffffu, acc0, 1);
        acc1 += __shfl_xor_sync(0xffffffffu, acc1, 1);

        // Scatter this round's 8 edge-sums into lanes 8r..8r+7.
        unsigned src = (i >> 1) << 3;
        float va = __shfl_sync(0xffffffffu, acc0, src);
        float vb = __shfl_sync(0xffffffffu, acc1, src);
        float val = (i & 1u) ? vb : va;
        if (grp == r) myacc = val;     // predicated select, no branch
    }

    // Tail: lanes 0..15 own edges base..base+15.
    if (lane < 16u) {
        float E = __expf(l * __logf(myacc + EPS_F));   // (d2+eps)^l
        float x = E * xv;              // exp(-logit_uv) = E*exp(-m_v)
        float y = E * xu;              // exp(-logit_vu) = E*exp(-m_u)
        float rr = __fdividef(1.0f, (1.0f + x) * (1.0f + y));

        float4 o;
        o.x = x * y * rr;   // p_nb
        o.y = y * rr;       // p_pu
        o.z = rr;           // p_pb
        o.w = x * rr;       // p_nu
        out[e_mine] = o;    // coalesced STG.128 (16 consecutive edges)
    }
}

extern "C" void kernel_launch(void* const* d_in, const int* in_sizes, int n_in,
                              void* d_out, int out_size) {
    const float* z    = (const float*)d_in[0];
    const float* l    = (const float*)d_in[1];
    const int*   eidx = (const int*)d_in[2];   // int64 in reference, but JAX
                                               // x64 is disabled -> int32
    float4*      out  = (float4*)d_out;

    // Repack (transpose + per-node exp): 196608 threads
    {
        int threads = 256;
        int quads = N_NODES * DIM / 4;
        int blocks = (quads + threads - 1) / threads;
        repack_kernel<<<blocks, threads>>>(z);
    }

    // Edge kernel: 16 edges per warp -> 16384 warps -> 2048 blocks of 256.
    {
        int threads = 256;
        int warps = N_EDGES / 16;
        int blocks = warps / (threads / 32);
        edge_kernel<<<blocks, threads>>>(eidx, l, out);
    }
}